// round 1
// baseline (speedup 1.0000x reference)
#include <cuda_runtime.h>
#include <cstdint>

// Problem constants
constexpr int B  = 8;
constexpr int C  = 19;
constexpr int H  = 320;
constexpr int W  = 2048;
constexpr int HH_OFF = 10;   // lab slice rows 10:20
constexpr int HH_N  = 10;
constexpr int WW   = 128;    // 2048/16
constexpr int P    = HH_N * WW;  // 1280
constexpr long long NE = (long long)B * P * P; // 13,107,200 elements per output tensor

// Scratch (no allocation allowed -> __device__ globals)
__device__ float g_sums[B * HH_N * WW * C];   // block sums per (b,hh,ww,c)
__device__ int   g_lab[B * P];                // argmax labels

// ---------------------------------------------------------------------------
// K1: per (b, hh, c) block computes 128 block-sums (one per ww).
// Block = 256 threads. Each thread streams 2 float4 per row, 16 rows.
// float4 index j within a row covers a single ww (ww = j/4).
// ---------------------------------------------------------------------------
__global__ __launch_bounds__(256) void pool_sum_kernel(const float* __restrict__ label)
{
    const int c  = blockIdx.x;   // 0..18
    const int hh = blockIdx.y;   // 0..9  (maps to pooled row HH_OFF+hh)
    const int b  = blockIdx.z;   // 0..7
    const int t  = threadIdx.x;  // 0..255

    const int h0 = (HH_OFF + hh) * 16;  // 160..304
    const float4* base = reinterpret_cast<const float4*>(
        label + (((size_t)b * C + c) * H + h0) * W);
    const int row_f4 = W / 4; // 512

    float acc0 = 0.f, acc1 = 0.f;
#pragma unroll 4
    for (int r = 0; r < 16; r++) {
        float4 v0 = base[(size_t)r * row_f4 + t];
        float4 v1 = base[(size_t)r * row_f4 + t + 256];
        acc0 += (v0.x + v0.y) + (v0.z + v0.w);
        acc1 += (v1.x + v1.y) + (v1.z + v1.w);
    }
    // Reduce across the 4 lanes sharing one ww (lanes 4k..4k+3)
    acc0 += __shfl_xor_sync(0xffffffffu, acc0, 1);
    acc0 += __shfl_xor_sync(0xffffffffu, acc0, 2);
    acc1 += __shfl_xor_sync(0xffffffffu, acc1, 1);
    acc1 += __shfl_xor_sync(0xffffffffu, acc1, 2);

    if ((t & 3) == 0) {
        const int ww0 = t >> 2;       // 0..63
        const int ww1 = ww0 + 64;     // 64..127
        const size_t rowbase = ((size_t)(b * HH_N + hh) * WW);
        g_sums[(rowbase + ww0) * C + c] = acc0;
        g_sums[(rowbase + ww1) * C + c] = acc1;
    }
}

// ---------------------------------------------------------------------------
// K2: argmax over 19 channels per pooled position -> g_lab. Tiny.
// Strict '>' reproduces jnp.argmax first-occurrence tie-break.
// ---------------------------------------------------------------------------
__global__ __launch_bounds__(256) void argmax_kernel()
{
    const int idx = blockIdx.x * 256 + threadIdx.x;
    if (idx >= B * P) return;
    const float* s = g_sums + (size_t)idx * C;
    float best = s[0];
    int bi = 0;
#pragma unroll
    for (int c = 1; c < C; c++) {
        float v = s[c];
        if (v > best) { best = v; bi = c; }
    }
    g_lab[idx] = bi;
}

// ---------------------------------------------------------------------------
// K3: per (b, row i): build e row from energy + label mask, softmax it,
// write e to out[0:NE) and attention_map to out[NE:2NE).
// Block = 256 threads, 5 elements/thread (P=1280).
// ---------------------------------------------------------------------------
__global__ __launch_bounds__(256) void attn_kernel(const float* __restrict__ energy,
                                                   float* __restrict__ out)
{
    const int i = blockIdx.x;   // 0..1279
    const int b = blockIdx.y;   // 0..7
    const int t = threadIdx.x;  // 0..255

    __shared__ int   lab_s[P];
    __shared__ float red_max[8];
    __shared__ float red_sum[8];

    const int* labrow = g_lab + b * P;
#pragma unroll
    for (int k = 0; k < 5; k++) lab_s[t + k * 256] = labrow[t + k * 256];
    __syncthreads();

    const int li = lab_s[i];
    const float* erow = energy + ((size_t)b * P + i) * P;

    float ev[5];
    float m = -1e30f;
#pragma unroll
    for (int k = 0; k < 5; k++) {
        const int j = t + k * 256;
        float en = erow[j];
        bool same = (lab_s[j] == li);
        // same:  e<0 -> 0.5 else energy ;  !same: e>0 -> -0.5 else energy
        float v = same ? (en < 0.f ? 0.5f : en)
                       : (en > 0.f ? -0.5f : en);
        ev[k] = v;
        m = fmaxf(m, v);
    }
    // block max
#pragma unroll
    for (int o = 16; o > 0; o >>= 1) m = fmaxf(m, __shfl_xor_sync(0xffffffffu, m, o));
    if ((t & 31) == 0) red_max[t >> 5] = m;
    __syncthreads();
    float bm = red_max[0];
#pragma unroll
    for (int w = 1; w < 8; w++) bm = fmaxf(bm, red_max[w]);

    float ex[5];
    float s = 0.f;
#pragma unroll
    for (int k = 0; k < 5; k++) {
        ex[k] = __expf(ev[k] - bm);
        s += ex[k];
    }
#pragma unroll
    for (int o = 16; o > 0; o >>= 1) s += __shfl_xor_sync(0xffffffffu, s, o);
    if ((t & 31) == 0) red_sum[t >> 5] = s;
    __syncthreads();
    float tot = red_sum[0];
#pragma unroll
    for (int w = 1; w < 8; w++) tot += red_sum[w];
    const float inv = 1.f / tot;

    float* eout = out + ((size_t)b * P + i) * P;
    float* aout = eout + NE;
#pragma unroll
    for (int k = 0; k < 5; k++) {
        const int j = t + k * 256;
        eout[j] = ev[k];
        aout[j] = ex[k] * inv;
    }
}

extern "C" void kernel_launch(void* const* d_in, const int* in_sizes, int n_in,
                              void* d_out, int out_size)
{
    const float* label  = (const float*)d_in[0];  // [8,19,320,2048] f32
    const float* energy = (const float*)d_in[1];  // [8,1280,1280]  f32
    float* out = (float*)d_out;                   // [2 * 8*1280*1280] f32 (e, attn)

    (void)in_sizes; (void)n_in; (void)out_size;

    dim3 g1(C, HH_N, B);
    pool_sum_kernel<<<g1, 256>>>(label);

    argmax_kernel<<<(B * P + 255) / 256, 256>>>();

    dim3 g3(P, B);
    attn_kernel<<<g3, 256>>>(energy, out);
}